// round 4
// baseline (speedup 1.0000x reference)
#include <cuda_runtime.h>
#include <cstdint>

#define N_NODES     8192
#define N_PAIRS_MAX 1000000
#define PATH_LEN    8
#define EDGE_DIM    16
#define MAX_EDGES   100000

#define HASH_BITS   22
#define HASH_SLOTS  (1u << HASH_BITS)
#define HASH_MASK   (HASH_SLOTS - 1u)

// Static device scratch (no allocs allowed).
__device__ float              g_dots[N_PAIRS_MAX];          // 4 MB
__device__ float              g_T[MAX_EDGES * PATH_LEN];    // 3.2 MB
__device__ unsigned long long g_hash[HASH_SLOTS];           // 32 MB

// ---------------------------------------------------------------------------
// Fast zero-fill: grid-stride float4 streaming stores (driver memset nodes
// only reach ~2.3 TB/s; this should reach ~5-6 TB/s).
// ---------------------------------------------------------------------------
__global__ void __launch_bounds__(256)
zero_fill4(float4* __restrict__ p, size_t n4)
{
    size_t i      = (size_t)blockIdx.x * blockDim.x + threadIdx.x;
    size_t stride = (size_t)gridDim.x * blockDim.x;
    const float4 z = make_float4(0.f, 0.f, 0.f, 0.f);
    for (; i < n4; i += stride) p[i] = z;
}

// ---------------------------------------------------------------------------
// T[e][l] = dot(edge_attr[e], edge_vector[l])
// ---------------------------------------------------------------------------
__global__ void __launch_bounds__(256)
precompute_T(const float* __restrict__ edge_attr,
             const float* __restrict__ edge_vector,
             int n_edges)
{
    int e = blockIdx.x * blockDim.x + threadIdx.x;
    if (e >= n_edges) return;

    const float4* ea = (const float4*)edge_attr + (size_t)e * 4;
    float4 a0 = __ldg(&ea[0]), a1 = __ldg(&ea[1]);
    float4 a2 = __ldg(&ea[2]), a3 = __ldg(&ea[3]);

    const float4* ev = (const float4*)edge_vector;
    float t[PATH_LEN];
#pragma unroll
    for (int l = 0; l < PATH_LEN; ++l) {
        float4 v0 = __ldg(&ev[l * 4 + 0]);
        float4 v1 = __ldg(&ev[l * 4 + 1]);
        float4 v2 = __ldg(&ev[l * 4 + 2]);
        float4 v3 = __ldg(&ev[l * 4 + 3]);
        t[l] = a0.x * v0.x + a0.y * v0.y + a0.z * v0.z + a0.w * v0.w
             + a1.x * v1.x + a1.y * v1.y + a1.z * v1.z + a1.w * v1.w
             + a2.x * v2.x + a2.y * v2.y + a2.z * v2.z + a2.w * v2.w
             + a3.x * v3.x + a3.y * v3.y + a3.z * v3.z + a3.w * v3.w;
    }
    float4* tt = (float4*)(g_T + (size_t)e * PATH_LEN);
    tt[0] = make_float4(t[0], t[1], t[2], t[3]);
    tt[1] = make_float4(t[4], t[5], t[6], t[7]);
}

// ---------------------------------------------------------------------------
// Per-pair masked mean via T-gather; claim (cell -> max pair idx) in hash.
// slot entry: key(=cell+1) << 24 | (p+1).
// ---------------------------------------------------------------------------
__global__ void __launch_bounds__(256)
pair_dots_claim(const int* __restrict__ paths,
                const int* __restrict__ src,
                const int* __restrict__ dst,
                int n_pairs)
{
    int p = blockIdx.x * blockDim.x + threadIdx.x;
    if (p >= n_pairs) return;

    const int4* pr = (const int4*)paths + (size_t)p * 2;
    int4 pa = pr[0];
    int4 pb = pr[1];
    int idxs[PATH_LEN] = {pa.x, pa.y, pa.z, pa.w, pb.x, pb.y, pb.z, pb.w};

    float sum = 0.0f;
#pragma unroll
    for (int l = 0; l < PATH_LEN; ++l) {
        int e = idxs[l];
        if (e >= 0) sum += __ldg(&g_T[(size_t)e * PATH_LEN + l]);
    }
    g_dots[p] = sum * (1.0f / PATH_LEN);

    unsigned cell = (unsigned)src[p] * N_NODES + (unsigned)dst[p]; // < 2^26
    unsigned key  = cell + 1u;                                     // != 0
    unsigned long long want = ((unsigned long long)key << 24) | (unsigned)(p + 1);
    unsigned slot = (cell * 2654435761u) >> (32 - HASH_BITS);

    while (true) {
        unsigned long long cur = g_hash[slot];
        if (cur == 0ULL) {
            unsigned long long prev = atomicCAS(&g_hash[slot], 0ULL, want);
            if (prev == 0ULL) return;
            cur = prev;
        }
        if ((unsigned)(cur >> 24) == key) {     // keys are write-once
            atomicMax(&g_hash[slot], want);     // same key -> compares p+1
            return;
        }
        slot = (slot + 1u) & HASH_MASK;
    }
}

// ---------------------------------------------------------------------------
// Coalesced sweep: every occupied slot is a winner record.
// ---------------------------------------------------------------------------
__global__ void __launch_bounds__(256)
fixup_scan(float* __restrict__ out)
{
    unsigned i = blockIdx.x * blockDim.x + threadIdx.x;
    if (i >= HASH_SLOTS) return;
    unsigned long long cur = g_hash[i];
    if (cur != 0ULL) {
        unsigned cell = (unsigned)(cur >> 24) - 1u;
        unsigned p    = (unsigned)(cur & 0xFFFFFFu) - 1u;
        out[cell] = g_dots[p];
    }
}

// ---------------------------------------------------------------------------
extern "C" void kernel_launch(void* const* d_in, const int* in_sizes, int n_in,
                              void* d_out, int out_size)
{
    int off = (in_sizes[0] == 1) ? 1 : 0;

    const float* edge_attr   = (const float*)d_in[off + 0];
    const int*   src         = (const int*)  d_in[off + 1];
    const int*   dst         = (const int*)  d_in[off + 2];
    const int*   paths       = (const int*)  d_in[off + 3];
    const float* edge_vector = (const float*)d_in[off + 4];
    float* out = (float*)d_out;

    const int n_edges = in_sizes[off + 0] / EDGE_DIM;
    const int n_pairs = in_sizes[off + 1];

    static cudaStream_t s2 = nullptr, s3 = nullptr;
    static cudaEvent_t  evF = nullptr, evOut = nullptr, evHash = nullptr;
    static bool inited = false;
    if (!inited) {
        bool ok = cudaStreamCreateWithFlags(&s2, cudaStreamNonBlocking) == cudaSuccess
               && cudaStreamCreateWithFlags(&s3, cudaStreamNonBlocking) == cudaSuccess
               && cudaEventCreateWithFlags(&evF,    cudaEventDisableTiming) == cudaSuccess
               && cudaEventCreateWithFlags(&evOut,  cudaEventDisableTiming) == cudaSuccess
               && cudaEventCreateWithFlags(&evHash, cudaEventDisableTiming) == cudaSuccess;
        if (!ok) { s2 = nullptr; s3 = nullptr; }
        inited = true;
    }

    void* hashp = nullptr;
    cudaGetSymbolAddress(&hashp, g_hash);
    const size_t out_n4  = (size_t)out_size / 4;                       // 16.7M float4
    const size_t hash_n4 = HASH_SLOTS * sizeof(unsigned long long) / 16;

    // Saturating grid for streaming fill: 148 SMs * 8 CTAs.
    const int fill_blocks = 148 * 8;

    if (s2) {
        cudaEventRecord(evF, 0);
        cudaStreamWaitEvent(s2, evF, 0);
        cudaStreamWaitEvent(s3, evF, 0);

        // s2: custom 256 MB zero-fill at streaming-write BW.
        zero_fill4<<<fill_blocks, 256, 0, s2>>>((float4*)out, out_n4);
        cudaEventRecord(evOut, s2);

        // s3: 32 MB hash zero-fill, concurrent with precompute_T.
        zero_fill4<<<fill_blocks, 256, 0, s3>>>((float4*)hashp, hash_n4);
        cudaEventRecord(evHash, s3);

        // stream 0: T table, then claims.
        precompute_T<<<(n_edges + 255) / 256, 256>>>(edge_attr, edge_vector, n_edges);

        cudaStreamWaitEvent(0, evHash, 0);
        pair_dots_claim<<<(n_pairs + 255) / 256, 256>>>(paths, src, dst, n_pairs);

        cudaStreamWaitEvent(0, evOut, 0);
        fixup_scan<<<HASH_SLOTS / 256, 256>>>(out);
    } else {
        zero_fill4<<<fill_blocks, 256>>>((float4*)out, out_n4);
        zero_fill4<<<fill_blocks, 256>>>((float4*)hashp, hash_n4);
        precompute_T<<<(n_edges + 255) / 256, 256>>>(edge_attr, edge_vector, n_edges);
        pair_dots_claim<<<(n_pairs + 255) / 256, 256>>>(paths, src, dst, n_pairs);
        fixup_scan<<<HASH_SLOTS / 256, 256>>>(out);
    }
}